// round 15
// baseline (speedup 1.0000x reference)
#include <cuda_runtime.h>
#include <cmath>

#define NMAX 20000

__device__ float  g_PHI[NMAX * 32];
__device__ float  g_ENV[NMAX];
__device__ float  g_F[NMAX * 192];
__device__ float4 g_WQ[6 * 16 * 64];   // [mat][c4][o] = W[o][4c4..4c4+3]

// ---------------------------------------------------------------------------
// Edge kernel: static 20-bin window anchored at group-aligned start s.
// One unrolled recurrence (no dynamic array -> registers only), then
// thresholded red.global.add.v4.f32 per 16B group (~3-4 REDs vs ~11 scalar).
// ---------------------------------------------------------------------------
__global__ void edge_kernel(const float* __restrict__ dist,
                            const int* __restrict__ nb, int E,
                            float mu0, float delta, float inv_delta,
                            float beta, float c2, float q)
{
    int e = blockIdx.x * blockDim.x + threadIdx.x;
    if (e >= E) return;
    float d = dist[e];
    int j = nb[e];
    float env = 0.0f;
    if (d < 5.0f) env = 0.5f * (__cosf(0.62831853071795864769f * d) + 1.0f);
    asm volatile("red.global.add.f32 [%0], %1;"
                 :: "l"(&g_ENV[j]), "f"(env) : "memory");

    float t = __expf(-d);
    int r0 = (int)floorf((t - mu0) * inv_delta + 0.5f);
    r0 = max(0, min(31, r0));
    int s = min(max(4 * (r0 >> 2) - 8, 0), 12);   // window [s, s+19], 16B-aligned

    float us = t - (mu0 + delta * (float)s);
    float p = env * __expf(-beta * us * us);
    float w = __expf(c2 * (t - (mu0 + delta * ((float)s + 0.5f))));

    float pv[20];
    pv[0] = p;
    #pragma unroll
    for (int i = 1; i < 20; ++i) { p *= w; w *= q; pv[i] = p; }

    float* phr = g_PHI + (size_t)j * 32 + s;
    #pragma unroll
    for (int g = 0; g < 5; ++g) {
        float a0 = pv[4 * g], a1 = pv[4 * g + 1];
        float a2 = pv[4 * g + 2], a3 = pv[4 * g + 3];
        if (a0 + a1 + a2 + a3 > 1e-10f) {
            asm volatile("red.global.add.v4.f32 [%0], {%1, %2, %3, %4};"
                         :: "l"(phr + 4 * g), "f"(a0), "f"(a1), "f"(a2), "f"(a3)
                         : "memory");
        }
    }
}

// ---------------------------------------------------------------------------
// Transform kernel: repack weights to [c4][o] float4 (coalesced, L1-resident).
// ---------------------------------------------------------------------------
__global__ void wq_kernel(const float* __restrict__ W0, const float* __restrict__ W1,
                          const float* __restrict__ W2, const float* __restrict__ W3,
                          const float* __restrict__ W4, const float* __restrict__ W5)
{
    int m = blockIdx.x;
    int idx = threadIdx.x;
    const float* Wsel = (m == 0) ? W0 : (m == 1) ? W1 : (m == 2) ? W2
                      : (m == 3) ? W3 : (m == 4) ? W4 : W5;
    int c4 = idx >> 6;
    int o  = idx & 63;
    g_WQ[m * 1024 + idx] = *(const float4*)(Wsel + o * 64 + c4 * 4);
}

// ---------------------------------------------------------------------------
// Coefficient kernel (parallel): 32 nodes/block, phi staged once, Wd in regs.
// F[n,o] = env[n]*bd[o] + Wd[o,:] . phi[n,:]
// ---------------------------------------------------------------------------
#define CB 32
__global__ void coeff_kernel(const float* __restrict__ Wd,
                             const float* __restrict__ bd, int N)
{
    __shared__ float ph[CB][33];
    int o = threadIdx.x;            // 0..191
    float wreg[32];
    const float4* wsrc = (const float4*)(Wd + (size_t)o * 32);
    #pragma unroll
    for (int i = 0; i < 8; ++i) {
        float4 v = wsrc[i];
        wreg[4 * i] = v.x; wreg[4 * i + 1] = v.y;
        wreg[4 * i + 2] = v.z; wreg[4 * i + 3] = v.w;
    }
    float b = bd[o];
    int nbase = blockIdx.x * CB;
    for (int idx = o; idx < CB * 32; idx += 192) {
        int n = idx >> 5, r = idx & 31;
        ph[n][r] = (nbase + n < N) ? g_PHI[(size_t)(nbase + n) * 32 + r] : 0.0f;
    }
    for (int idx = o; idx < CB; idx += 192)
        ph[idx][32] = (nbase + idx < N) ? g_ENV[nbase + idx] : 0.0f;
    __syncthreads();
    #pragma unroll 4
    for (int n = 0; n < CB; ++n) {
        if (nbase + n >= N) break;
        float acc = ph[n][32] * b;
        #pragma unroll
        for (int r = 0; r < 32; ++r) acc += wreg[r] * ph[n][r];
        g_F[(size_t)(nbase + n) * 192 + o] = acc;
    }
}

// ---------------------------------------------------------------------------
// f32x2 packed FMA helpers
// ---------------------------------------------------------------------------
__device__ __forceinline__ void ffma2(unsigned long long& d,
                                      unsigned long long a,
                                      unsigned long long b)
{
    asm("fma.rn.f32x2 %0, %1, %2, %0;" : "+l"(d) : "l"(a), "l"(b));
}
__device__ __forceinline__ float sum2(unsigned long long v)
{
    float lo, hi;
    asm("mov.b64 {%0, %1}, %2;" : "=f"(lo), "=f"(hi) : "l"(v));
    return lo + hi;
}
__device__ __forceinline__ void split4(float4 v, unsigned long long& lo,
                                       unsigned long long& hi)
{
    asm("mov.b64 %0, {%2, %3}; mov.b64 %1, {%4, %5};"
        : "=l"(lo), "=l"(hi) : "f"(v.x), "f"(v.y), "f"(v.z), "f"(v.w));
}

__device__ __forceinline__ void decomp9(const float x[9], float* iso,
                                        float a[3], float s[5])
{
    float m = (x[0] + x[4] + x[8]) * (1.0f / 3.0f);
    *iso = m;
    a[0] = 0.5f * (x[1] - x[3]);
    a[1] = 0.5f * (x[2] - x[6]);
    a[2] = 0.5f * (x[5] - x[7]);
    s[0] = x[0] - m;
    s[1] = 0.5f * (x[1] + x[3]);
    s[2] = 0.5f * (x[2] + x[6]);
    s[3] = x[4] - m;
    s[4] = 0.5f * (x[5] + x[7]);
}

__device__ __forceinline__ void build9(float iso, const float a[3],
                                       const float s[5], float Y[9])
{
    Y[0] = iso + s[0];        Y[1] = a[0] + s[1];       Y[2] = a[1] + s[2];
    Y[3] = s[1] - a[0];       Y[4] = iso + s[3];        Y[5] = a[2] + s[4];
    Y[6] = s[2] - a[1];       Y[7] = s[4] - a[2];       Y[8] = iso - s[0] - s[3];
}

// ---------------------------------------------------------------------------
// Node kernel: 256 threads = 4 pairs, GRP=3 nodes/pair, 3 blocks/SM (24 warps).
// Weights from L1-resident g_WQ; k-split (warp0: A 0-2 + iso 8; warp1: S 3-7);
// M preserved via out-scratch (same-thread write/read).
// ---------------------------------------------------------------------------
#define GRP 3
#define PLANE 68
#define CPSZ (9 * PLANE)            // 612 per node
#define PSZ 2416                    // cp 3*612=1836 | xs 576 | pad 4
#define SMEM_FLOATS (4 * PSZ)       // 9664 floats = 38,656 B per block

#define PAIR_BAR() asm volatile("bar.sync %0, 64;" :: "r"(barid) : "memory")

__device__ __forceinline__ void mix_stage(const float4* __restrict__ WQA,
                                          const float4* __restrict__ WQS,
                                          const float4* __restrict__ WQI,
                                          float* __restrict__ cp,
                                          int lane, int half)
{
    if (half == 0) {
        unsigned long long accA[3][2][GRP] = {};
        unsigned long long accI[2][GRP] = {};
        #pragma unroll 4
        for (int j = 0; j < 16; ++j) {
            unsigned long long a0x, a0y, a1x, a1y, i0x, i0y, i1x, i1y;
            split4(__ldg(&WQA[j * 64 + lane]),      a0x, a0y);
            split4(__ldg(&WQA[j * 64 + lane + 32]), a1x, a1y);
            split4(__ldg(&WQI[j * 64 + lane]),      i0x, i0y);
            split4(__ldg(&WQI[j * 64 + lane + 32]), i1x, i1y);
            #pragma unroll
            for (int n = 0; n < GRP; ++n) {
                const float* base = cp + n * CPSZ + 4 * j;
                #pragma unroll
                for (int k = 0; k < 3; ++k) {
                    ulonglong2 m = *(const ulonglong2*)(base + k * PLANE);
                    ffma2(accA[k][0][n], a0x, m.x);
                    ffma2(accA[k][0][n], a0y, m.y);
                    ffma2(accA[k][1][n], a1x, m.x);
                    ffma2(accA[k][1][n], a1y, m.y);
                }
                ulonglong2 m8 = *(const ulonglong2*)(base + 8 * PLANE);
                ffma2(accI[0][n], i0x, m8.x);
                ffma2(accI[0][n], i0y, m8.y);
                ffma2(accI[1][n], i1x, m8.x);
                ffma2(accI[1][n], i1y, m8.y);
            }
        }
        __syncwarp();
        #pragma unroll
        for (int n = 0; n < GRP; ++n) {
            float* cpn = cp + n * CPSZ;
            #pragma unroll
            for (int h = 0; h < 2; ++h) {
                int ch = lane + 32 * h;
                cpn[0 * PLANE + ch] = sum2(accA[0][h][n]);
                cpn[1 * PLANE + ch] = sum2(accA[1][h][n]);
                cpn[2 * PLANE + ch] = sum2(accA[2][h][n]);
                cpn[8 * PLANE + ch] = sum2(accI[h][n]);
            }
        }
    } else {
        unsigned long long accS[5][2][GRP] = {};
        #pragma unroll 4
        for (int j = 0; j < 16; ++j) {
            unsigned long long s0x, s0y, s1x, s1y;
            split4(__ldg(&WQS[j * 64 + lane]),      s0x, s0y);
            split4(__ldg(&WQS[j * 64 + lane + 32]), s1x, s1y);
            #pragma unroll
            for (int n = 0; n < GRP; ++n) {
                const float* base = cp + n * CPSZ + 3 * PLANE + 4 * j;
                #pragma unroll
                for (int k = 0; k < 5; ++k) {
                    ulonglong2 m = *(const ulonglong2*)(base + k * PLANE);
                    ffma2(accS[k][0][n], s0x, m.x);
                    ffma2(accS[k][0][n], s0y, m.y);
                    ffma2(accS[k][1][n], s1x, m.x);
                    ffma2(accS[k][1][n], s1y, m.y);
                }
            }
        }
        __syncwarp();
        #pragma unroll
        for (int n = 0; n < GRP; ++n) {
            float* cpn = cp + n * CPSZ;
            #pragma unroll
            for (int h = 0; h < 2; ++h) {
                int ch = lane + 32 * h;
                #pragma unroll
                for (int k = 0; k < 5; ++k)
                    cpn[(3 + k) * PLANE + ch] = sum2(accS[k][h][n]);
            }
        }
    }
}

__global__ __launch_bounds__(256, 3)
void node_kernel(const float* __restrict__ X, float* __restrict__ out, int N)
{
    extern __shared__ float sm[];
    int tid   = threadIdx.x;
    int lane  = tid & 31;
    int pair  = tid >> 6;             // 0..3
    int half  = (tid >> 5) & 1;
    int c     = lane + 32 * half;
    int pid   = tid & 63;
    int barid = pair + 1;

    float* cp = sm + pair * PSZ;      // 3 * 612 comp planes
    float* xs = cp + GRP * CPSZ;      // 576 staging

    const float4* WQAa = g_WQ + 0 * 1024;
    const float4* WQSa = g_WQ + 1 * 1024;
    const float4* WQIa = g_WQ + 2 * 1024;
    const float4* WQAb = g_WQ + 3 * 1024;
    const float4* WQSb = g_WQ + 4 * 1024;
    const float4* WQIb = g_WQ + 5 * 1024;

    int Q = (N + GRP - 1) / GRP;
    int gp = blockIdx.x * 4 + pair;
    int step = gridDim.x * 4;

    for (int q = gp; q < Q; q += step) {
        int n0 = q * GRP;

        // ---- coefficients (precomputed) ----
        float fI[GRP], fA[GRP], fS[GRP];
        #pragma unroll
        for (int n = 0; n < GRP; ++n) {
            int node = min(n0 + n, N - 1);
            const float* Fn = g_F + (size_t)node * 192;
            fI[n] = Fn[c];
            fA[n] = Fn[64 + c];
            fS[n] = Fn[128 + c];
        }

        // ---- per node: stage X, decompose -> cp planes + folded-M to out ---
        #pragma unroll
        for (int n = 0; n < GRP; ++n) {
            int node = n0 + n;
            if (node < N) {
                const float4* src = (const float4*)(X + (size_t)node * 576);
                float4* dst = (float4*)xs;
                #pragma unroll
                for (int i = 0; i < 3; ++i) {
                    int idx = pid + 64 * i;
                    if (idx < 144) dst[idx] = src[idx];
                }
            }
            PAIR_BAR();
            if (node < N) {
                float x[9];
                #pragma unroll
                for (int k = 0; k < 9; ++k) x[k] = xs[c * 9 + k];
                float f = 0.0f;
                #pragma unroll
                for (int k = 0; k < 9; ++k) f += x[k] * x[k];
                float sc = __fdividef(1.0f, f + 1.0f);
                #pragma unroll
                for (int k = 0; k < 9; ++k) x[k] *= sc;
                float iso, a[3], s[5];
                decomp9(x, &iso, a, s);
                float* cpn = cp + n * CPSZ;
                cpn[0 * PLANE + c] = a[0];
                cpn[1 * PLANE + c] = a[1];
                cpn[2 * PLANE + c] = a[2];
                cpn[3 * PLANE + c] = s[0];
                cpn[4 * PLANE + c] = s[1];
                cpn[5 * PLANE + c] = s[2];
                cpn[6 * PLANE + c] = s[3];
                cpn[7 * PLANE + c] = s[4];
                cpn[8 * PLANE + c] = iso;
                float* mo = out + (size_t)node * 576;
                mo[0 * 64 + c] = fA[n] * a[0];
                mo[1 * 64 + c] = fA[n] * a[1];
                mo[2 * 64 + c] = fA[n] * a[2];
                mo[3 * 64 + c] = fS[n] * s[0];
                mo[4 * 64 + c] = fS[n] * s[1];
                mo[5 * 64 + c] = fS[n] * s[2];
                mo[6 * 64 + c] = fS[n] * s[3];
                mo[7 * 64 + c] = fS[n] * s[4];
                mo[8 * 64 + c] = fI[n] * iso;
            }
            PAIR_BAR();
        }

        // ---- pre mix (k-split, L1-resident weights) ----
        mix_stage(WQAa, WQSa, WQIa, cp, lane, half);
        PAIR_BAR();

        // ---- sandwich: Z = YM + MY (M from out-scratch), norm, decompose ---
        #pragma unroll
        for (int n = 0; n < GRP; ++n) {
            int node = n0 + n;
            if (node < N) {
                float* cpn = cp + n * CPSZ;
                const float* mo = out + (size_t)node * 576;
                float yv[9], mv[9];
                #pragma unroll
                for (int k = 0; k < 9; ++k) {
                    yv[k] = cpn[k * PLANE + c];
                    mv[k] = mo[k * 64 + c];     // same thread wrote it
                }
                float Y[9], M[9];
                build9(yv[8], &yv[0], &yv[3], Y);
                build9(mv[8], &mv[0], &mv[3], M);
                float Z[9];
                #pragma unroll
                for (int i = 0; i < 3; ++i)
                    #pragma unroll
                    for (int jj = 0; jj < 3; ++jj) {
                        float acc = 0.0f;
                        #pragma unroll
                        for (int k = 0; k < 3; ++k)
                            acc += Y[i * 3 + k] * M[k * 3 + jj]
                                 + M[i * 3 + k] * Y[k * 3 + jj];
                        Z[i * 3 + jj] = acc;
                    }
                float nrm = 0.0f;
                #pragma unroll
                for (int k = 0; k < 9; ++k) { float v = Z[k] + 1.0f; nrm += v * v; }
                float inv = __fdividef(1.0f, nrm);
                #pragma unroll
                for (int k = 0; k < 9; ++k) Z[k] *= inv;
                float iso, a2[3], s2[5];
                decomp9(Z, &iso, a2, s2);
                cpn[0 * PLANE + c] = a2[0];
                cpn[1 * PLANE + c] = a2[1];
                cpn[2 * PLANE + c] = a2[2];
                cpn[3 * PLANE + c] = s2[0];
                cpn[4 * PLANE + c] = s2[1];
                cpn[5 * PLANE + c] = s2[2];
                cpn[6 * PLANE + c] = s2[3];
                cpn[7 * PLANE + c] = s2[4];
                cpn[8 * PLANE + c] = iso;
            }
        }
        PAIR_BAR();

        // ---- post mix ----
        mix_stage(WQAb, WQSb, WQIb, cp, lane, half);
        PAIR_BAR();

        // ---- output: O = Y2 + Y2@Y2, stage per node, pair-coalesced store --
        #pragma unroll
        for (int n = 0; n < GRP; ++n) {
            int node = n0 + n;
            {
                float* cpn = cp + n * CPSZ;
                float yv[9];
                #pragma unroll
                for (int k = 0; k < 9; ++k) yv[k] = cpn[k * PLANE + c];
                float Y2[9];
                build9(yv[8], &yv[0], &yv[3], Y2);
                float* od = xs + c * 9;
                #pragma unroll
                for (int i = 0; i < 3; ++i)
                    #pragma unroll
                    for (int jj = 0; jj < 3; ++jj) {
                        float acc = Y2[i * 3 + jj];
                        #pragma unroll
                        for (int k = 0; k < 3; ++k)
                            acc += Y2[i * 3 + k] * Y2[k * 3 + jj];
                        od[i * 3 + jj] = acc;
                    }
            }
            PAIR_BAR();
            if (node < N) {
                float4* dst = (float4*)(out + (size_t)node * 576);
                const float4* src = (const float4*)xs;
                #pragma unroll
                for (int i = 0; i < 3; ++i) {
                    int idx = pid + 64 * i;
                    if (idx < 144) dst[idx] = src[idx];
                }
            }
            PAIR_BAR();
        }
    }
}

// ---------------------------------------------------------------------------
extern "C" void kernel_launch(void* const* d_in, const int* in_sizes, int n_in,
                              void* d_out, int out_size)
{
    const float* X    = (const float*)d_in[0];
    const float* dist = (const float*)d_in[1];
    const int*   nb   = (const int*)d_in[2];
    const float* WIa  = (const float*)d_in[3];
    const float* WAa  = (const float*)d_in[4];
    const float* WSa  = (const float*)d_in[5];
    const float* WIb  = (const float*)d_in[6];
    const float* WAb  = (const float*)d_in[7];
    const float* WSb  = (const float*)d_in[8];
    const float* Wd   = (const float*)d_in[9];
    const float* bd   = (const float*)d_in[10];
    float* out = (float*)d_out;

    int N = in_sizes[0] / 576;
    int E = in_sizes[1];

    void* phi_ptr = nullptr;
    void* env_ptr = nullptr;
    cudaGetSymbolAddress(&phi_ptr, g_PHI);
    cudaGetSymbolAddress(&env_ptr, g_ENV);
    cudaMemsetAsync(phi_ptr, 0, sizeof(float) * (size_t)N * 32, 0);
    cudaMemsetAsync(env_ptr, 0, sizeof(float) * (size_t)N, 0);

    double e5    = exp(-5.0);
    double delta = (1.0 - e5) / 31.0;
    double bb    = (2.0 / 32.0) * (1.0 - e5);
    double beta  = 1.0 / (bb * bb);
    float  c2    = (float)(2.0 * beta * delta);
    float  qf    = (float)exp(-2.0 * beta * delta * delta);

    wq_kernel<<<6, 1024>>>(WAa, WSa, WIa, WAb, WSb, WIb);
    edge_kernel<<<(E + 255) / 256, 256>>>(dist, nb, E,
        (float)e5, (float)delta, (float)(1.0 / delta), (float)beta, c2, qf);
    coeff_kernel<<<(N + CB - 1) / CB, 192>>>(Wd, bd, N);

    node_kernel<<<444, 256, SMEM_FLOATS * sizeof(float)>>>(X, out, N);
}

// round 16
// speedup vs baseline: 1.8599x; 1.8599x over previous
#include <cuda_runtime.h>
#include <cmath>

#define NMAX 20000

__device__ float  g_PHI[NMAX * 32];
__device__ float  g_ENV[NMAX];
__device__ float  g_F[NMAX * 192];
__device__ float4 g_WQ[6 * 16 * 64];   // [mat][c4][o] = W[o][4c4..4c4+3]

// ---------------------------------------------------------------------------
// Edge kernel: static 20-bin window, unrolled recurrence, thresholded v4 REDs.
// ---------------------------------------------------------------------------
__global__ void edge_kernel(const float* __restrict__ dist,
                            const int* __restrict__ nb, int E,
                            float mu0, float delta, float inv_delta,
                            float beta, float c2, float q)
{
    int e = blockIdx.x * blockDim.x + threadIdx.x;
    if (e >= E) return;
    float d = dist[e];
    int j = nb[e];
    float env = 0.0f;
    if (d < 5.0f) env = 0.5f * (__cosf(0.62831853071795864769f * d) + 1.0f);
    asm volatile("red.global.add.f32 [%0], %1;"
                 :: "l"(&g_ENV[j]), "f"(env) : "memory");

    float t = __expf(-d);
    int r0 = (int)floorf((t - mu0) * inv_delta + 0.5f);
    r0 = max(0, min(31, r0));
    int s = min(max(4 * (r0 >> 2) - 8, 0), 12);   // window [s, s+19]

    float us = t - (mu0 + delta * (float)s);
    float p = env * __expf(-beta * us * us);
    float w = __expf(c2 * (t - (mu0 + delta * ((float)s + 0.5f))));

    float pv[20];
    pv[0] = p;
    #pragma unroll
    for (int i = 1; i < 20; ++i) { p *= w; w *= q; pv[i] = p; }

    float* phr = g_PHI + (size_t)j * 32 + s;
    #pragma unroll
    for (int g = 0; g < 5; ++g) {
        float a0 = pv[4 * g], a1 = pv[4 * g + 1];
        float a2 = pv[4 * g + 2], a3 = pv[4 * g + 3];
        if (a0 + a1 + a2 + a3 > 1e-10f) {
            asm volatile("red.global.add.v4.f32 [%0], {%1, %2, %3, %4};"
                         :: "l"(phr + 4 * g), "f"(a0), "f"(a1), "f"(a2), "f"(a3)
                         : "memory");
        }
    }
}

// ---------------------------------------------------------------------------
// Transform kernel: repack weights to [c4][o] float4 (coalesced, L1-resident).
// ---------------------------------------------------------------------------
__global__ void wq_kernel(const float* __restrict__ W0, const float* __restrict__ W1,
                          const float* __restrict__ W2, const float* __restrict__ W3,
                          const float* __restrict__ W4, const float* __restrict__ W5)
{
    int m = blockIdx.x;
    int idx = threadIdx.x;
    const float* Wsel = (m == 0) ? W0 : (m == 1) ? W1 : (m == 2) ? W2
                      : (m == 3) ? W3 : (m == 4) ? W4 : W5;
    int c4 = idx >> 6;
    int o  = idx & 63;
    g_WQ[m * 1024 + idx] = *(const float4*)(Wsel + o * 64 + c4 * 4);
}

// ---------------------------------------------------------------------------
// Coefficient kernel (parallel): 32 nodes/block, phi staged once, Wd in regs.
// ---------------------------------------------------------------------------
#define CB 32
__global__ void coeff_kernel(const float* __restrict__ Wd,
                             const float* __restrict__ bd, int N)
{
    __shared__ float ph[CB][33];
    int o = threadIdx.x;            // 0..191
    float wreg[32];
    const float4* wsrc = (const float4*)(Wd + (size_t)o * 32);
    #pragma unroll
    for (int i = 0; i < 8; ++i) {
        float4 v = wsrc[i];
        wreg[4 * i] = v.x; wreg[4 * i + 1] = v.y;
        wreg[4 * i + 2] = v.z; wreg[4 * i + 3] = v.w;
    }
    float b = bd[o];
    int nbase = blockIdx.x * CB;
    for (int idx = o; idx < CB * 32; idx += 192) {
        int n = idx >> 5, r = idx & 31;
        ph[n][r] = (nbase + n < N) ? g_PHI[(size_t)(nbase + n) * 32 + r] : 0.0f;
    }
    for (int idx = o; idx < CB; idx += 192)
        ph[idx][32] = (nbase + idx < N) ? g_ENV[nbase + idx] : 0.0f;
    __syncthreads();
    #pragma unroll 4
    for (int n = 0; n < CB; ++n) {
        if (nbase + n >= N) break;
        float acc = ph[n][32] * b;
        #pragma unroll
        for (int r = 0; r < 32; ++r) acc += wreg[r] * ph[n][r];
        g_F[(size_t)(nbase + n) * 192 + o] = acc;
    }
}

// ---------------------------------------------------------------------------
// f32x2 packed FMA helpers
// ---------------------------------------------------------------------------
__device__ __forceinline__ void ffma2(unsigned long long& d,
                                      unsigned long long a,
                                      unsigned long long b)
{
    asm("fma.rn.f32x2 %0, %1, %2, %0;" : "+l"(d) : "l"(a), "l"(b));
}
__device__ __forceinline__ float sum2(unsigned long long v)
{
    float lo, hi;
    asm("mov.b64 {%0, %1}, %2;" : "=f"(lo), "=f"(hi) : "l"(v));
    return lo + hi;
}
__device__ __forceinline__ void split4(float4 v, unsigned long long& lo,
                                       unsigned long long& hi)
{
    asm("mov.b64 %0, {%2, %3}; mov.b64 %1, {%4, %5};"
        : "=l"(lo), "=l"(hi) : "f"(v.x), "f"(v.y), "f"(v.z), "f"(v.w));
}

__device__ __forceinline__ void decomp9(const float x[9], float* iso,
                                        float a[3], float s[5])
{
    float m = (x[0] + x[4] + x[8]) * (1.0f / 3.0f);
    *iso = m;
    a[0] = 0.5f * (x[1] - x[3]);
    a[1] = 0.5f * (x[2] - x[6]);
    a[2] = 0.5f * (x[5] - x[7]);
    s[0] = x[0] - m;
    s[1] = 0.5f * (x[1] + x[3]);
    s[2] = 0.5f * (x[2] + x[6]);
    s[3] = x[4] - m;
    s[4] = 0.5f * (x[5] + x[7]);
}

__device__ __forceinline__ void build9(float iso, const float a[3],
                                       const float s[5], float Y[9])
{
    Y[0] = iso + s[0];        Y[1] = a[0] + s[1];       Y[2] = a[1] + s[2];
    Y[3] = s[1] - a[0];       Y[4] = iso + s[3];        Y[5] = a[2] + s[4];
    Y[6] = s[2] - a[1];       Y[7] = s[4] - a[2];       Y[8] = iso - s[0] - s[3];
}

// ---------------------------------------------------------------------------
// Node kernel: 256 threads = 4 pairs, GRP=2 nodes/pair, 3 blocks/SM (24 warps).
// Weights from L1-resident g_WQ; k-split (warp0: A 0-2 + iso 8; warp1: S 3-7);
// M preserved in a second smem plane set cpM (no global round-trip).
// ---------------------------------------------------------------------------
#define GRP 2
#define PLANE 68
#define CPSZ (9 * PLANE)            // 612 per node
#define PSZ 3032                    // cp 1224 | cpM 1224 | xs 576 | pad 8
#define SMEM_FLOATS (4 * PSZ)       // 12128 floats = 48,512 B per block

#define PAIR_BAR() asm volatile("bar.sync %0, 64;" :: "r"(barid) : "memory")

__device__ __forceinline__ void mix_stage(const float4* __restrict__ WQA,
                                          const float4* __restrict__ WQS,
                                          const float4* __restrict__ WQI,
                                          float* __restrict__ cp,
                                          int lane, int half)
{
    if (half == 0) {
        unsigned long long accA[3][2][GRP] = {};
        unsigned long long accI[2][GRP] = {};
        #pragma unroll 4
        for (int j = 0; j < 16; ++j) {
            unsigned long long a0x, a0y, a1x, a1y, i0x, i0y, i1x, i1y;
            split4(__ldg(&WQA[j * 64 + lane]),      a0x, a0y);
            split4(__ldg(&WQA[j * 64 + lane + 32]), a1x, a1y);
            split4(__ldg(&WQI[j * 64 + lane]),      i0x, i0y);
            split4(__ldg(&WQI[j * 64 + lane + 32]), i1x, i1y);
            #pragma unroll
            for (int n = 0; n < GRP; ++n) {
                const float* base = cp + n * CPSZ + 4 * j;
                #pragma unroll
                for (int k = 0; k < 3; ++k) {
                    ulonglong2 m = *(const ulonglong2*)(base + k * PLANE);
                    ffma2(accA[k][0][n], a0x, m.x);
                    ffma2(accA[k][0][n], a0y, m.y);
                    ffma2(accA[k][1][n], a1x, m.x);
                    ffma2(accA[k][1][n], a1y, m.y);
                }
                ulonglong2 m8 = *(const ulonglong2*)(base + 8 * PLANE);
                ffma2(accI[0][n], i0x, m8.x);
                ffma2(accI[0][n], i0y, m8.y);
                ffma2(accI[1][n], i1x, m8.x);
                ffma2(accI[1][n], i1y, m8.y);
            }
        }
        __syncwarp();
        #pragma unroll
        for (int n = 0; n < GRP; ++n) {
            float* cpn = cp + n * CPSZ;
            #pragma unroll
            for (int h = 0; h < 2; ++h) {
                int ch = lane + 32 * h;
                cpn[0 * PLANE + ch] = sum2(accA[0][h][n]);
                cpn[1 * PLANE + ch] = sum2(accA[1][h][n]);
                cpn[2 * PLANE + ch] = sum2(accA[2][h][n]);
                cpn[8 * PLANE + ch] = sum2(accI[h][n]);
            }
        }
    } else {
        unsigned long long accS[5][2][GRP] = {};
        #pragma unroll 4
        for (int j = 0; j < 16; ++j) {
            unsigned long long s0x, s0y, s1x, s1y;
            split4(__ldg(&WQS[j * 64 + lane]),      s0x, s0y);
            split4(__ldg(&WQS[j * 64 + lane + 32]), s1x, s1y);
            #pragma unroll
            for (int n = 0; n < GRP; ++n) {
                const float* base = cp + n * CPSZ + 3 * PLANE + 4 * j;
                #pragma unroll
                for (int k = 0; k < 5; ++k) {
                    ulonglong2 m = *(const ulonglong2*)(base + k * PLANE);
                    ffma2(accS[k][0][n], s0x, m.x);
                    ffma2(accS[k][0][n], s0y, m.y);
                    ffma2(accS[k][1][n], s1x, m.x);
                    ffma2(accS[k][1][n], s1y, m.y);
                }
            }
        }
        __syncwarp();
        #pragma unroll
        for (int n = 0; n < GRP; ++n) {
            float* cpn = cp + n * CPSZ;
            #pragma unroll
            for (int h = 0; h < 2; ++h) {
                int ch = lane + 32 * h;
                #pragma unroll
                for (int k = 0; k < 5; ++k)
                    cpn[(3 + k) * PLANE + ch] = sum2(accS[k][h][n]);
            }
        }
    }
}

__global__ __launch_bounds__(256, 3)
void node_kernel(const float* __restrict__ X, float* __restrict__ out, int N)
{
    extern __shared__ float sm[];
    int tid   = threadIdx.x;
    int lane  = tid & 31;
    int pair  = tid >> 6;             // 0..3
    int half  = (tid >> 5) & 1;
    int c     = lane + 32 * half;
    int pid   = tid & 63;
    int barid = pair + 1;

    float* cp  = sm + pair * PSZ;     // 2 * 612 mix planes
    float* cpM = cp + GRP * CPSZ;     // 2 * 612 preserved-M planes
    float* xs  = cpM + GRP * CPSZ;    // 576 staging

    const float4* WQAa = g_WQ + 0 * 1024;
    const float4* WQSa = g_WQ + 1 * 1024;
    const float4* WQIa = g_WQ + 2 * 1024;
    const float4* WQAb = g_WQ + 3 * 1024;
    const float4* WQSb = g_WQ + 4 * 1024;
    const float4* WQIb = g_WQ + 5 * 1024;

    int Q = (N + GRP - 1) / GRP;
    int gp = blockIdx.x * 4 + pair;
    int step = gridDim.x * 4;

    for (int q = gp; q < Q; q += step) {
        int n0 = q * GRP;

        // ---- coefficients (precomputed) ----
        float fI[GRP], fA[GRP], fS[GRP];
        #pragma unroll
        for (int n = 0; n < GRP; ++n) {
            int node = min(n0 + n, N - 1);
            const float* Fn = g_F + (size_t)node * 192;
            fI[n] = Fn[c];
            fA[n] = Fn[64 + c];
            fS[n] = Fn[128 + c];
        }

        // ---- per node: stage X, decompose -> cp planes + folded-M to cpM ---
        #pragma unroll
        for (int n = 0; n < GRP; ++n) {
            int node = n0 + n;
            if (node < N) {
                const float4* src = (const float4*)(X + (size_t)node * 576);
                float4* dst = (float4*)xs;
                #pragma unroll
                for (int i = 0; i < 3; ++i) {
                    int idx = pid + 64 * i;
                    if (idx < 144) dst[idx] = src[idx];
                }
            }
            PAIR_BAR();
            if (node < N) {
                float x[9];
                #pragma unroll
                for (int k = 0; k < 9; ++k) x[k] = xs[c * 9 + k];
                float f = 0.0f;
                #pragma unroll
                for (int k = 0; k < 9; ++k) f += x[k] * x[k];
                float sc = __fdividef(1.0f, f + 1.0f);
                #pragma unroll
                for (int k = 0; k < 9; ++k) x[k] *= sc;
                float iso, a[3], s[5];
                decomp9(x, &iso, a, s);
                float* cpn  = cp  + n * CPSZ;
                float* cpMn = cpM + n * CPSZ;
                cpn[0 * PLANE + c] = a[0];
                cpn[1 * PLANE + c] = a[1];
                cpn[2 * PLANE + c] = a[2];
                cpn[3 * PLANE + c] = s[0];
                cpn[4 * PLANE + c] = s[1];
                cpn[5 * PLANE + c] = s[2];
                cpn[6 * PLANE + c] = s[3];
                cpn[7 * PLANE + c] = s[4];
                cpn[8 * PLANE + c] = iso;
                cpMn[0 * PLANE + c] = fA[n] * a[0];
                cpMn[1 * PLANE + c] = fA[n] * a[1];
                cpMn[2 * PLANE + c] = fA[n] * a[2];
                cpMn[3 * PLANE + c] = fS[n] * s[0];
                cpMn[4 * PLANE + c] = fS[n] * s[1];
                cpMn[5 * PLANE + c] = fS[n] * s[2];
                cpMn[6 * PLANE + c] = fS[n] * s[3];
                cpMn[7 * PLANE + c] = fS[n] * s[4];
                cpMn[8 * PLANE + c] = fI[n] * iso;
            }
            PAIR_BAR();
        }

        // ---- pre mix (k-split, L1-resident weights) ----
        mix_stage(WQAa, WQSa, WQIa, cp, lane, half);
        PAIR_BAR();

        // ---- sandwich: Z = YM + MY (M from cpM), norm, decompose ----
        #pragma unroll
        for (int n = 0; n < GRP; ++n) {
            int node = n0 + n;
            if (node < N) {
                float* cpn  = cp  + n * CPSZ;
                float* cpMn = cpM + n * CPSZ;
                float yv[9], mv[9];
                #pragma unroll
                for (int k = 0; k < 9; ++k) {
                    yv[k] = cpn[k * PLANE + c];
                    mv[k] = cpMn[k * PLANE + c];
                }
                float Y[9], M[9];
                build9(yv[8], &yv[0], &yv[3], Y);
                build9(mv[8], &mv[0], &mv[3], M);
                float Z[9];
                #pragma unroll
                for (int i = 0; i < 3; ++i)
                    #pragma unroll
                    for (int jj = 0; jj < 3; ++jj) {
                        float acc = 0.0f;
                        #pragma unroll
                        for (int k = 0; k < 3; ++k)
                            acc += Y[i * 3 + k] * M[k * 3 + jj]
                                 + M[i * 3 + k] * Y[k * 3 + jj];
                        Z[i * 3 + jj] = acc;
                    }
                float nrm = 0.0f;
                #pragma unroll
                for (int k = 0; k < 9; ++k) { float v = Z[k] + 1.0f; nrm += v * v; }
                float inv = __fdividef(1.0f, nrm);
                #pragma unroll
                for (int k = 0; k < 9; ++k) Z[k] *= inv;
                float iso, a2[3], s2[5];
                decomp9(Z, &iso, a2, s2);
                cpn[0 * PLANE + c] = a2[0];
                cpn[1 * PLANE + c] = a2[1];
                cpn[2 * PLANE + c] = a2[2];
                cpn[3 * PLANE + c] = s2[0];
                cpn[4 * PLANE + c] = s2[1];
                cpn[5 * PLANE + c] = s2[2];
                cpn[6 * PLANE + c] = s2[3];
                cpn[7 * PLANE + c] = s2[4];
                cpn[8 * PLANE + c] = iso;
            }
        }
        PAIR_BAR();

        // ---- post mix ----
        mix_stage(WQAb, WQSb, WQIb, cp, lane, half);
        PAIR_BAR();

        // ---- output: O = Y2 + Y2@Y2, stage per node, pair-coalesced store --
        #pragma unroll
        for (int n = 0; n < GRP; ++n) {
            int node = n0 + n;
            {
                float* cpn = cp + n * CPSZ;
                float yv[9];
                #pragma unroll
                for (int k = 0; k < 9; ++k) yv[k] = cpn[k * PLANE + c];
                float Y2[9];
                build9(yv[8], &yv[0], &yv[3], Y2);
                float* od = xs + c * 9;
                #pragma unroll
                for (int i = 0; i < 3; ++i)
                    #pragma unroll
                    for (int jj = 0; jj < 3; ++jj) {
                        float acc = Y2[i * 3 + jj];
                        #pragma unroll
                        for (int k = 0; k < 3; ++k)
                            acc += Y2[i * 3 + k] * Y2[k * 3 + jj];
                        od[i * 3 + jj] = acc;
                    }
            }
            PAIR_BAR();
            if (node < N) {
                float4* dst = (float4*)(out + (size_t)node * 576);
                const float4* src = (const float4*)xs;
                #pragma unroll
                for (int i = 0; i < 3; ++i) {
                    int idx = pid + 64 * i;
                    if (idx < 144) dst[idx] = src[idx];
                }
            }
            PAIR_BAR();
        }
    }
}

// ---------------------------------------------------------------------------
extern "C" void kernel_launch(void* const* d_in, const int* in_sizes, int n_in,
                              void* d_out, int out_size)
{
    const float* X    = (const float*)d_in[0];
    const float* dist = (const float*)d_in[1];
    const int*   nb   = (const int*)d_in[2];
    const float* WIa  = (const float*)d_in[3];
    const float* WAa  = (const float*)d_in[4];
    const float* WSa  = (const float*)d_in[5];
    const float* WIb  = (const float*)d_in[6];
    const float* WAb  = (const float*)d_in[7];
    const float* WSb  = (const float*)d_in[8];
    const float* Wd   = (const float*)d_in[9];
    const float* bd   = (const float*)d_in[10];
    float* out = (float*)d_out;

    int N = in_sizes[0] / 576;
    int E = in_sizes[1];

    void* phi_ptr = nullptr;
    void* env_ptr = nullptr;
    cudaGetSymbolAddress(&phi_ptr, g_PHI);
    cudaGetSymbolAddress(&env_ptr, g_ENV);
    cudaMemsetAsync(phi_ptr, 0, sizeof(float) * (size_t)N * 32, 0);
    cudaMemsetAsync(env_ptr, 0, sizeof(float) * (size_t)N, 0);

    double e5    = exp(-5.0);
    double delta = (1.0 - e5) / 31.0;
    double bb    = (2.0 / 32.0) * (1.0 - e5);
    double beta  = 1.0 / (bb * bb);
    float  c2    = (float)(2.0 * beta * delta);
    float  qf    = (float)exp(-2.0 * beta * delta * delta);

    wq_kernel<<<6, 1024>>>(WAa, WSa, WIa, WAb, WSb, WIb);
    edge_kernel<<<(E + 255) / 256, 256>>>(dist, nb, E,
        (float)e5, (float)delta, (float)(1.0 / delta), (float)beta, c2, qf);
    coeff_kernel<<<(N + CB - 1) / CB, 192>>>(Wd, bd, N);

    static int smem_set = 0;
    if (!smem_set) {
        cudaFuncSetAttribute(node_kernel,
                             cudaFuncAttributeMaxDynamicSharedMemorySize,
                             SMEM_FLOATS * sizeof(float));
        smem_set = 1;
    }
    node_kernel<<<444, 256, SMEM_FLOATS * sizeof(float)>>>(X, out, N);
}

// round 17
// speedup vs baseline: 1.8651x; 1.0028x over previous
#include <cuda_runtime.h>
#include <cmath>

#define NMAX 20000

__device__ float  g_PHI[NMAX * 32];
__device__ float  g_ENV[NMAX];
__device__ float  g_F[NMAX * 192];
__device__ float4 g_WQ[6 * 16 * 64];   // [mat][c4][o] = W[o][4c4..4c4+3]

// ---------------------------------------------------------------------------
// Edge kernel: static 20-bin window, unrolled recurrence, thresholded v4 REDs.
// ---------------------------------------------------------------------------
__global__ void edge_kernel(const float* __restrict__ dist,
                            const int* __restrict__ nb, int E,
                            float mu0, float delta, float inv_delta,
                            float beta, float c2, float q)
{
    int e = blockIdx.x * blockDim.x + threadIdx.x;
    if (e >= E) return;
    float d = dist[e];
    int j = nb[e];
    float env = 0.0f;
    if (d < 5.0f) env = 0.5f * (__cosf(0.62831853071795864769f * d) + 1.0f);
    asm volatile("red.global.add.f32 [%0], %1;"
                 :: "l"(&g_ENV[j]), "f"(env) : "memory");

    float t = __expf(-d);
    int r0 = (int)floorf((t - mu0) * inv_delta + 0.5f);
    r0 = max(0, min(31, r0));
    int s = min(max(4 * (r0 >> 2) - 8, 0), 12);   // window [s, s+19]

    float us = t - (mu0 + delta * (float)s);
    float p = env * __expf(-beta * us * us);
    float w = __expf(c2 * (t - (mu0 + delta * ((float)s + 0.5f))));

    float pv[20];
    pv[0] = p;
    #pragma unroll
    for (int i = 1; i < 20; ++i) { p *= w; w *= q; pv[i] = p; }

    float* phr = g_PHI + (size_t)j * 32 + s;
    #pragma unroll
    for (int g = 0; g < 5; ++g) {
        float a0 = pv[4 * g], a1 = pv[4 * g + 1];
        float a2 = pv[4 * g + 2], a3 = pv[4 * g + 3];
        if (a0 + a1 + a2 + a3 > 1e-10f) {
            asm volatile("red.global.add.v4.f32 [%0], {%1, %2, %3, %4};"
                         :: "l"(phr + 4 * g), "f"(a0), "f"(a1), "f"(a2), "f"(a3)
                         : "memory");
        }
    }
}

// ---------------------------------------------------------------------------
// Transform kernel: repack weights to [c4][o] float4 (coalesced, L1-resident).
// ---------------------------------------------------------------------------
__global__ void wq_kernel(const float* __restrict__ W0, const float* __restrict__ W1,
                          const float* __restrict__ W2, const float* __restrict__ W3,
                          const float* __restrict__ W4, const float* __restrict__ W5)
{
    int m = blockIdx.x;
    int idx = threadIdx.x;
    const float* Wsel = (m == 0) ? W0 : (m == 1) ? W1 : (m == 2) ? W2
                      : (m == 3) ? W3 : (m == 4) ? W4 : W5;
    int c4 = idx >> 6;
    int o  = idx & 63;
    g_WQ[m * 1024 + idx] = *(const float4*)(Wsel + o * 64 + c4 * 4);
}

// ---------------------------------------------------------------------------
// Coefficient kernel (parallel): 32 nodes/block, phi staged once, Wd in regs.
// ---------------------------------------------------------------------------
#define CB 32
__global__ void coeff_kernel(const float* __restrict__ Wd,
                             const float* __restrict__ bd, int N)
{
    __shared__ float ph[CB][33];
    int o = threadIdx.x;            // 0..191
    float wreg[32];
    const float4* wsrc = (const float4*)(Wd + (size_t)o * 32);
    #pragma unroll
    for (int i = 0; i < 8; ++i) {
        float4 v = wsrc[i];
        wreg[4 * i] = v.x; wreg[4 * i + 1] = v.y;
        wreg[4 * i + 2] = v.z; wreg[4 * i + 3] = v.w;
    }
    float b = bd[o];
    int nbase = blockIdx.x * CB;
    for (int idx = o; idx < CB * 32; idx += 192) {
        int n = idx >> 5, r = idx & 31;
        ph[n][r] = (nbase + n < N) ? g_PHI[(size_t)(nbase + n) * 32 + r] : 0.0f;
    }
    for (int idx = o; idx < CB; idx += 192)
        ph[idx][32] = (nbase + idx < N) ? g_ENV[nbase + idx] : 0.0f;
    __syncthreads();
    #pragma unroll 4
    for (int n = 0; n < CB; ++n) {
        if (nbase + n >= N) break;
        float acc = ph[n][32] * b;
        #pragma unroll
        for (int r = 0; r < 32; ++r) acc += wreg[r] * ph[n][r];
        g_F[(size_t)(nbase + n) * 192 + o] = acc;
    }
}

// ---------------------------------------------------------------------------
// f32x2 packed FMA helpers
// ---------------------------------------------------------------------------
__device__ __forceinline__ void ffma2(unsigned long long& d,
                                      unsigned long long a,
                                      unsigned long long b)
{
    asm("fma.rn.f32x2 %0, %1, %2, %0;" : "+l"(d) : "l"(a), "l"(b));
}
__device__ __forceinline__ float sum2(unsigned long long v)
{
    float lo, hi;
    asm("mov.b64 {%0, %1}, %2;" : "=f"(lo), "=f"(hi) : "l"(v));
    return lo + hi;
}
// direct 16B weight load as two u64 (no float4->u64 repack)
__device__ __forceinline__ void ldg2u64(const float4* p,
                                        unsigned long long& lo,
                                        unsigned long long& hi)
{
    asm("ld.global.nc.v2.u64 {%0, %1}, [%2];" : "=l"(lo), "=l"(hi) : "l"(p));
}

__device__ __forceinline__ void decomp9(const float x[9], float* iso,
                                        float a[3], float s[5])
{
    float m = (x[0] + x[4] + x[8]) * (1.0f / 3.0f);
    *iso = m;
    a[0] = 0.5f * (x[1] - x[3]);
    a[1] = 0.5f * (x[2] - x[6]);
    a[2] = 0.5f * (x[5] - x[7]);
    s[0] = x[0] - m;
    s[1] = 0.5f * (x[1] + x[3]);
    s[2] = 0.5f * (x[2] + x[6]);
    s[3] = x[4] - m;
    s[4] = 0.5f * (x[5] + x[7]);
}

__device__ __forceinline__ void build9(float iso, const float a[3],
                                       const float s[5], float Y[9])
{
    Y[0] = iso + s[0];        Y[1] = a[0] + s[1];       Y[2] = a[1] + s[2];
    Y[3] = s[1] - a[0];       Y[4] = iso + s[3];        Y[5] = a[2] + s[4];
    Y[6] = s[2] - a[1];       Y[7] = s[4] - a[2];       Y[8] = iso - s[0] - s[3];
}

// ---------------------------------------------------------------------------
// Node kernel: 256 threads = 4 pairs, GRP=2 nodes/pair, 3 blocks/SM (24 warps).
// Weights from L1-resident g_WQ; k-split (warp0: A 0-2 + iso 8; warp1: S 3-7);
// M preserved in smem cpM. Batched 2-node staging/output: 7 bars per group.
// ---------------------------------------------------------------------------
#define GRP 2
#define PLANE 68
#define CPSZ (9 * PLANE)            // 612 per node
#define PSZ 3608                    // cp 1224 | cpM 1224 | xs 1152 | pad 8
#define SMEM_FLOATS (4 * PSZ)       // 14432 floats = 57,728 B per block

#define PAIR_BAR() asm volatile("bar.sync %0, 64;" :: "r"(barid) : "memory")

__device__ __forceinline__ void mix_stage(const float4* __restrict__ WQA,
                                          const float4* __restrict__ WQS,
                                          const float4* __restrict__ WQI,
                                          float* __restrict__ cp,
                                          int lane, int half)
{
    if (half == 0) {
        unsigned long long accA[3][2][GRP] = {};
        unsigned long long accI[2][GRP] = {};
        #pragma unroll 4
        for (int j = 0; j < 16; ++j) {
            unsigned long long a0x, a0y, a1x, a1y, i0x, i0y, i1x, i1y;
            ldg2u64(&WQA[j * 64 + lane],      a0x, a0y);
            ldg2u64(&WQA[j * 64 + lane + 32], a1x, a1y);
            ldg2u64(&WQI[j * 64 + lane],      i0x, i0y);
            ldg2u64(&WQI[j * 64 + lane + 32], i1x, i1y);
            #pragma unroll
            for (int n = 0; n < GRP; ++n) {
                const float* base = cp + n * CPSZ + 4 * j;
                #pragma unroll
                for (int k = 0; k < 3; ++k) {
                    ulonglong2 m = *(const ulonglong2*)(base + k * PLANE);
                    ffma2(accA[k][0][n], a0x, m.x);
                    ffma2(accA[k][0][n], a0y, m.y);
                    ffma2(accA[k][1][n], a1x, m.x);
                    ffma2(accA[k][1][n], a1y, m.y);
                }
                ulonglong2 m8 = *(const ulonglong2*)(base + 8 * PLANE);
                ffma2(accI[0][n], i0x, m8.x);
                ffma2(accI[0][n], i0y, m8.y);
                ffma2(accI[1][n], i1x, m8.x);
                ffma2(accI[1][n], i1y, m8.y);
            }
        }
        __syncwarp();
        #pragma unroll
        for (int n = 0; n < GRP; ++n) {
            float* cpn = cp + n * CPSZ;
            #pragma unroll
            for (int h = 0; h < 2; ++h) {
                int ch = lane + 32 * h;
                cpn[0 * PLANE + ch] = sum2(accA[0][h][n]);
                cpn[1 * PLANE + ch] = sum2(accA[1][h][n]);
                cpn[2 * PLANE + ch] = sum2(accA[2][h][n]);
                cpn[8 * PLANE + ch] = sum2(accI[h][n]);
            }
        }
    } else {
        unsigned long long accS[5][2][GRP] = {};
        #pragma unroll 4
        for (int j = 0; j < 16; ++j) {
            unsigned long long s0x, s0y, s1x, s1y;
            ldg2u64(&WQS[j * 64 + lane],      s0x, s0y);
            ldg2u64(&WQS[j * 64 + lane + 32], s1x, s1y);
            #pragma unroll
            for (int n = 0; n < GRP; ++n) {
                const float* base = cp + n * CPSZ + 3 * PLANE + 4 * j;
                #pragma unroll
                for (int k = 0; k < 5; ++k) {
                    ulonglong2 m = *(const ulonglong2*)(base + k * PLANE);
                    ffma2(accS[k][0][n], s0x, m.x);
                    ffma2(accS[k][0][n], s0y, m.y);
                    ffma2(accS[k][1][n], s1x, m.x);
                    ffma2(accS[k][1][n], s1y, m.y);
                }
            }
        }
        __syncwarp();
        #pragma unroll
        for (int n = 0; n < GRP; ++n) {
            float* cpn = cp + n * CPSZ;
            #pragma unroll
            for (int h = 0; h < 2; ++h) {
                int ch = lane + 32 * h;
                #pragma unroll
                for (int k = 0; k < 5; ++k)
                    cpn[(3 + k) * PLANE + ch] = sum2(accS[k][h][n]);
            }
        }
    }
}

__global__ __launch_bounds__(256, 3)
void node_kernel(const float* __restrict__ X, float* __restrict__ out, int N)
{
    extern __shared__ float sm[];
    int tid   = threadIdx.x;
    int lane  = tid & 31;
    int pair  = tid >> 6;             // 0..3
    int half  = (tid >> 5) & 1;
    int c     = lane + 32 * half;
    int pid   = tid & 63;
    int barid = pair + 1;

    float* cp  = sm + pair * PSZ;     // 2 * 612 mix planes
    float* cpM = cp + GRP * CPSZ;     // 2 * 612 preserved-M planes
    float* xs  = cpM + GRP * CPSZ;    // 1152 staging (both nodes)

    const float4* WQAa = g_WQ + 0 * 1024;
    const float4* WQSa = g_WQ + 1 * 1024;
    const float4* WQIa = g_WQ + 2 * 1024;
    const float4* WQAb = g_WQ + 3 * 1024;
    const float4* WQSb = g_WQ + 4 * 1024;
    const float4* WQIb = g_WQ + 5 * 1024;

    int Q = (N + GRP - 1) / GRP;
    int gp = blockIdx.x * 4 + pair;
    int step = gridDim.x * 4;

    for (int q = gp; q < Q; q += step) {
        int n0 = q * GRP;
        int nvalid = min(N - n0, GRP);
        int cnt4 = nvalid * 144;

        // ---- coefficients (precomputed; early to hide latency) ----
        float fI[GRP], fA[GRP], fS[GRP];
        #pragma unroll
        for (int n = 0; n < GRP; ++n) {
            int node = min(n0 + n, N - 1);
            const float* Fn = g_F + (size_t)node * 192;
            fI[n] = Fn[c];
            fA[n] = Fn[64 + c];
            fS[n] = Fn[128 + c];
        }

        // ---- stage BOTH nodes' X in one coalesced burst ----
        {
            const float4* src = (const float4*)(X + (size_t)n0 * 576);
            float4* dst = (float4*)xs;
            #pragma unroll
            for (int i = 0; i < 5; ++i) {
                int idx = pid + 64 * i;
                if (idx < cnt4) dst[idx] = src[idx];
            }
        }
        PAIR_BAR();

        // ---- decompose both nodes (own channel) -> cp planes + cpM ----
        #pragma unroll
        for (int n = 0; n < GRP; ++n) {
            int node = n0 + n;
            if (node < N) {
                float x[9];
                #pragma unroll
                for (int k = 0; k < 9; ++k) x[k] = xs[n * 576 + c * 9 + k];
                float f = 0.0f;
                #pragma unroll
                for (int k = 0; k < 9; ++k) f += x[k] * x[k];
                float sc = __fdividef(1.0f, f + 1.0f);
                #pragma unroll
                for (int k = 0; k < 9; ++k) x[k] *= sc;
                float iso, a[3], s[5];
                decomp9(x, &iso, a, s);
                float* cpn  = cp  + n * CPSZ;
                float* cpMn = cpM + n * CPSZ;
                cpn[0 * PLANE + c] = a[0];
                cpn[1 * PLANE + c] = a[1];
                cpn[2 * PLANE + c] = a[2];
                cpn[3 * PLANE + c] = s[0];
                cpn[4 * PLANE + c] = s[1];
                cpn[5 * PLANE + c] = s[2];
                cpn[6 * PLANE + c] = s[3];
                cpn[7 * PLANE + c] = s[4];
                cpn[8 * PLANE + c] = iso;
                cpMn[0 * PLANE + c] = fA[n] * a[0];
                cpMn[1 * PLANE + c] = fA[n] * a[1];
                cpMn[2 * PLANE + c] = fA[n] * a[2];
                cpMn[3 * PLANE + c] = fS[n] * s[0];
                cpMn[4 * PLANE + c] = fS[n] * s[1];
                cpMn[5 * PLANE + c] = fS[n] * s[2];
                cpMn[6 * PLANE + c] = fS[n] * s[3];
                cpMn[7 * PLANE + c] = fS[n] * s[4];
                cpMn[8 * PLANE + c] = fI[n] * iso;
            }
        }
        PAIR_BAR();

        // ---- pre mix (k-split, L1-resident weights) ----
        mix_stage(WQAa, WQSa, WQIa, cp, lane, half);
        PAIR_BAR();

        // ---- sandwich: Z = YM + MY (M from cpM), norm, decompose ----
        #pragma unroll
        for (int n = 0; n < GRP; ++n) {
            int node = n0 + n;
            if (node < N) {
                float* cpn  = cp  + n * CPSZ;
                float* cpMn = cpM + n * CPSZ;
                float yv[9], mv[9];
                #pragma unroll
                for (int k = 0; k < 9; ++k) {
                    yv[k] = cpn[k * PLANE + c];
                    mv[k] = cpMn[k * PLANE + c];
                }
                float Y[9], M[9];
                build9(yv[8], &yv[0], &yv[3], Y);
                build9(mv[8], &mv[0], &mv[3], M);
                float Z[9];
                #pragma unroll
                for (int i = 0; i < 3; ++i)
                    #pragma unroll
                    for (int jj = 0; jj < 3; ++jj) {
                        float acc = 0.0f;
                        #pragma unroll
                        for (int k = 0; k < 3; ++k)
                            acc += Y[i * 3 + k] * M[k * 3 + jj]
                                 + M[i * 3 + k] * Y[k * 3 + jj];
                        Z[i * 3 + jj] = acc;
                    }
                float nrm = 0.0f;
                #pragma unroll
                for (int k = 0; k < 9; ++k) { float v = Z[k] + 1.0f; nrm += v * v; }
                float inv = __fdividef(1.0f, nrm);
                #pragma unroll
                for (int k = 0; k < 9; ++k) Z[k] *= inv;
                float iso, a2[3], s2[5];
                decomp9(Z, &iso, a2, s2);
                cpn[0 * PLANE + c] = a2[0];
                cpn[1 * PLANE + c] = a2[1];
                cpn[2 * PLANE + c] = a2[2];
                cpn[3 * PLANE + c] = s2[0];
                cpn[4 * PLANE + c] = s2[1];
                cpn[5 * PLANE + c] = s2[2];
                cpn[6 * PLANE + c] = s2[3];
                cpn[7 * PLANE + c] = s2[4];
                cpn[8 * PLANE + c] = iso;
            }
        }
        PAIR_BAR();

        // ---- post mix ----
        mix_stage(WQAb, WQSb, WQIb, cp, lane, half);
        PAIR_BAR();

        // ---- output: O = Y2 + Y2@Y2, build BOTH nodes, one coalesced store -
        #pragma unroll
        for (int n = 0; n < GRP; ++n) {
            float* cpn = cp + n * CPSZ;
            float yv[9];
            #pragma unroll
            for (int k = 0; k < 9; ++k) yv[k] = cpn[k * PLANE + c];
            float Y2[9];
            build9(yv[8], &yv[0], &yv[3], Y2);
            float* od = xs + n * 576 + c * 9;
            #pragma unroll
            for (int i = 0; i < 3; ++i)
                #pragma unroll
                for (int jj = 0; jj < 3; ++jj) {
                    float acc = Y2[i * 3 + jj];
                    #pragma unroll
                    for (int k = 0; k < 3; ++k)
                        acc += Y2[i * 3 + k] * Y2[k * 3 + jj];
                    od[i * 3 + jj] = acc;
                }
        }
        PAIR_BAR();
        {
            float4* dst = (float4*)(out + (size_t)n0 * 576);
            const float4* src = (const float4*)xs;
            #pragma unroll
            for (int i = 0; i < 5; ++i) {
                int idx = pid + 64 * i;
                if (idx < cnt4) dst[idx] = src[idx];
            }
        }
        PAIR_BAR();   // xs fully read before next iteration's staging
    }
}

// ---------------------------------------------------------------------------
extern "C" void kernel_launch(void* const* d_in, const int* in_sizes, int n_in,
                              void* d_out, int out_size)
{
    const float* X    = (const float*)d_in[0];
    const float* dist = (const float*)d_in[1];
    const int*   nb   = (const int*)d_in[2];
    const float* WIa  = (const float*)d_in[3];
    const float* WAa  = (const float*)d_in[4];
    const float* WSa  = (const float*)d_in[5];
    const float* WIb  = (const float*)d_in[6];
    const float* WAb  = (const float*)d_in[7];
    const float* WSb  = (const float*)d_in[8];
    const float* Wd   = (const float*)d_in[9];
    const float* bd   = (const float*)d_in[10];
    float* out = (float*)d_out;

    int N = in_sizes[0] / 576;
    int E = in_sizes[1];

    void* phi_ptr = nullptr;
    void* env_ptr = nullptr;
    cudaGetSymbolAddress(&phi_ptr, g_PHI);
    cudaGetSymbolAddress(&env_ptr, g_ENV);
    cudaMemsetAsync(phi_ptr, 0, sizeof(float) * (size_t)N * 32, 0);
    cudaMemsetAsync(env_ptr, 0, sizeof(float) * (size_t)N, 0);

    double e5    = exp(-5.0);
    double delta = (1.0 - e5) / 31.0;
    double bb    = (2.0 / 32.0) * (1.0 - e5);
    double beta  = 1.0 / (bb * bb);
    float  c2    = (float)(2.0 * beta * delta);
    float  qf    = (float)exp(-2.0 * beta * delta * delta);

    wq_kernel<<<6, 1024>>>(WAa, WSa, WIa, WAb, WSb, WIb);
    edge_kernel<<<(E + 255) / 256, 256>>>(dist, nb, E,
        (float)e5, (float)delta, (float)(1.0 / delta), (float)beta, c2, qf);
    coeff_kernel<<<(N + CB - 1) / CB, 192>>>(Wd, bd, N);

    static int smem_set = 0;
    if (!smem_set) {
        cudaFuncSetAttribute(node_kernel,
                             cudaFuncAttributeMaxDynamicSharedMemorySize,
                             SMEM_FLOATS * sizeof(float));
        smem_set = 1;
    }
    node_kernel<<<444, 256, SMEM_FLOATS * sizeof(float)>>>(X, out, N);
}